// round 1
// baseline (speedup 1.0000x reference)
#include <cuda_runtime.h>
#include <math.h>
#include <stdint.h>

#define BATCH 1024
#define SEQ   128
#define EMB   1024
#define HID   1024
#define NCLS  50257
#define G4    (4 * HID)   // 4096

// ---- scratch (device globals; no runtime allocation) ----
__device__ float g_E[(size_t)NCLS * G4];     // token -> precomputed x-projection row (823 MB)
__device__ float g_h[BATCH * HID];
__device__ float g_c[BATCH * HID];
__device__ float g_gates[BATCH * G4];

__device__ __forceinline__ float sigmoidf_(float x) {
    return 1.0f / (1.0f + expf(-x));
}

// ---------------------------------------------------------------------------
// Generic row-major GEMM: Cout[M,N] = A[M,K] @ B[K,N]  (+ epilogue by EPI)
//   EPI 0: A = Ap (C table), Cout = g_E, plain store        (M=50257 edge)
//   EPI 1: A = g_h, Cout = g_gates, += g_E[tok] + bx + bh   (exact tiles)
//   EPI 2: A = g_h, Cout = Cp (d_out), += b_out             (N=50257 edge)
// Tiling: 128x128x16, 256 threads, 8x8 per thread.
// ---------------------------------------------------------------------------
template <int EPI>
__global__ void __launch_bounds__(256, 2) gemm_k(
    const float* __restrict__ Ap, const float* __restrict__ B,
    float* __restrict__ Cp,
    int M, int N, int K,
    const float* __restrict__ bias1, const float* __restrict__ bias2,
    const int* __restrict__ Xtok, int s)
{
    const float* A    = (EPI == 0) ? Ap : g_h;
    float*       Cout = (EPI == 0) ? g_E : (EPI == 1) ? g_gates : Cp;

    __shared__ float As[16][128];   // transposed A tile: As[k][m]
    __shared__ float Bs[16][128];   // Bs[k][n]

    const int tid  = threadIdx.x;
    const int m0   = blockIdx.y * 128;
    const int n0   = blockIdx.x * 128;
    const int tcol = tid & 15;      // 16 thread-cols * 8 = 128
    const int trow = tid >> 4;      // 16 thread-rows * 8 = 128

    float acc[8][8];
#pragma unroll
    for (int i = 0; i < 8; i++)
#pragma unroll
        for (int j = 0; j < 8; j++) acc[i][j] = 0.0f;

    for (int k0 = 0; k0 < K; k0 += 16) {
        // ---- load A tile (float4; rows are 16B aligned since K=1024) ----
#pragma unroll
        for (int i = 0; i < 2; i++) {
            int v   = tid + i * 256;        // float4 index 0..511
            int row = v >> 2;               // 0..127
            int c4  = (v & 3) * 4;          // 0,4,8,12
            float4 a;
            if (m0 + row < M)
                a = *(const float4*)&A[(size_t)(m0 + row) * K + k0 + c4];
            else
                a = make_float4(0.f, 0.f, 0.f, 0.f);
            As[c4 + 0][row] = a.x;
            As[c4 + 1][row] = a.y;
            As[c4 + 2][row] = a.z;
            As[c4 + 3][row] = a.w;
        }
        // ---- load B tile (scalar: N=50257 rows are only 4B aligned) ----
#pragma unroll
        for (int i = 0; i < 8; i++) {
            int v = tid + i * 256;          // 0..2047
            int r = v >> 7;                 // 0..15
            int c = v & 127;
            float b = 0.0f;
            if (n0 + c < N) b = B[(size_t)(k0 + r) * N + n0 + c];
            Bs[r][c] = b;
        }
        __syncthreads();

#pragma unroll
        for (int k = 0; k < 16; k++) {
            float4 a0 = *(const float4*)&As[k][trow * 8];
            float4 a1 = *(const float4*)&As[k][trow * 8 + 4];
            float4 b0 = *(const float4*)&Bs[k][tcol * 8];
            float4 b1 = *(const float4*)&Bs[k][tcol * 8 + 4];
            float ar[8] = {a0.x, a0.y, a0.z, a0.w, a1.x, a1.y, a1.z, a1.w};
            float br[8] = {b0.x, b0.y, b0.z, b0.w, b1.x, b1.y, b1.z, b1.w};
#pragma unroll
            for (int i = 0; i < 8; i++)
#pragma unroll
                for (int j = 0; j < 8; j++)
                    acc[i][j] = fmaf(ar[i], br[j], acc[i][j]);
        }
        __syncthreads();
    }

    // ---- epilogue ----
#pragma unroll
    for (int i = 0; i < 8; i++) {
        int row = m0 + trow * 8 + i;
        if (row >= M) continue;
        const float* erow = nullptr;
        if (EPI == 1) {
            int tok = Xtok[row * SEQ + s];
            erow = &g_E[(size_t)tok * G4];
        }
#pragma unroll
        for (int j = 0; j < 8; j++) {
            int col = n0 + tcol * 8 + j;
            if (col >= N) continue;
            float v = acc[i][j];
            if (EPI == 1) v += erow[col] + bias1[col] + bias2[col];
            if (EPI == 2) v += bias1[col];
            Cout[(size_t)row * N + col] = v;
        }
    }
}

// ---------------------------------------------------------------------------
__global__ void zero_hc_k() {
    int idx = blockIdx.x * blockDim.x + threadIdx.x;
    if (idx < BATCH * HID) {
        g_h[idx] = 0.0f;
        g_c[idx] = 0.0f;
    }
}

__global__ void cell_update_k() {
    int idx = blockIdx.x * blockDim.x + threadIdx.x;   // 0 .. BATCH*HID-1
    int b = idx >> 10;        // /HID
    int j = idx & 1023;       // %HID
    const float* gr = &g_gates[(size_t)b * G4];
    float ig = sigmoidf_(gr[j]);
    float fg = sigmoidf_(gr[j + HID]);
    float gg = tanhf(gr[j + 2 * HID]);
    float og = sigmoidf_(gr[j + 3 * HID]);
    float c  = fg * g_c[idx] + ig * gg;
    g_c[idx] = c;
    g_h[idx] = og * tanhf(c);
}

// ---------------------------------------------------------------------------
extern "C" void kernel_launch(void* const* d_in, const int* in_sizes, int n_in,
                              void* d_out, int out_size)
{
    const int*   X     = (const int*)  d_in[0];
    const float* C     = (const float*)d_in[1];
    const float* Wx    = (const float*)d_in[2];
    const float* bx    = (const float*)d_in[3];
    const float* Wh    = (const float*)d_in[4];
    const float* bh    = (const float*)d_in[5];
    const float* W_out = (const float*)d_in[6];
    const float* b_out = (const float*)d_in[7];
    float* out = (float*)d_out;

    (void)in_sizes; (void)n_in; (void)out_size;

    // init h, c = 0
    zero_hc_k<<<(BATCH * HID + 255) / 256, 256>>>();

    // Phase 1: E = C @ Wx   [50257,1024] x [1024,4096]
    {
        dim3 grid(G4 / 128, (NCLS + 127) / 128);
        gemm_k<0><<<grid, 256>>>(C, Wx, nullptr, NCLS, G4, EMB,
                                 nullptr, nullptr, nullptr, 0);
    }

    // Phase 2: 128 LSTM steps:  gates = E[X[:,s]] + bx + h @ Wh + bh ; cell update
    {
        dim3 grid(G4 / 128, BATCH / 128);
        for (int s = 0; s < SEQ; s++) {
            gemm_k<1><<<grid, 256>>>(nullptr, Wh, nullptr, BATCH, G4, HID,
                                     bx, bh, X, s);
            cell_update_k<<<(BATCH * HID) / 256, 256>>>();
        }
    }

    // Phase 3: out = h @ W_out + b_out   [1024,1024] x [1024,50257]
    {
        dim3 grid((NCLS + 127) / 128, BATCH / 128);
        gemm_k<2><<<grid, 256>>>(nullptr, W_out, out, BATCH, NCLS, HID,
                                 b_out, nullptr, nullptr, 0);
    }
}

// round 4
// speedup vs baseline: 2.1575x; 2.1575x over previous
#include <cuda_runtime.h>
#include <cuda_bf16.h>
#include <math.h>
#include <stdint.h>

#define BATCH 1024
#define SEQ   128
#define KDIM  1024
#define G4    4096
#define NCLS  50257

#define TM 128
#define TN 128
#define KC 32
#define NK (KDIM / KC)        // 32
#define STAGES 3

#define OPB   10240           // 128 rows * 80 bytes
#define STGB  (4 * OPB)       // Ah, Al, Bh, Bl
#define SMEM_BYTES (STAGES * STGB)   // 122880

// ---------------- device scratch (static, no runtime alloc) ----------------
__device__ __nv_bfloat16 g_Ch[(size_t)NCLS * KDIM];
__device__ __nv_bfloat16 g_Cl[(size_t)NCLS * KDIM];
__device__ __nv_bfloat16 g_WxTh[(size_t)G4 * KDIM];
__device__ __nv_bfloat16 g_WxTl[(size_t)G4 * KDIM];
__device__ __nv_bfloat16 g_WhTh[(size_t)G4 * KDIM];
__device__ __nv_bfloat16 g_WhTl[(size_t)G4 * KDIM];
__device__ __nv_bfloat16 g_WoTh[(size_t)NCLS * KDIM];
__device__ __nv_bfloat16 g_WoTl[(size_t)NCLS * KDIM];
__device__ float g_E[(size_t)NCLS * G4];
__device__ float g_gates[(size_t)BATCH * G4];
__device__ float g_c[(size_t)BATCH * KDIM];
__device__ __nv_bfloat16 g_hh[(size_t)BATCH * KDIM];
__device__ __nv_bfloat16 g_hl[(size_t)BATCH * KDIM];

// ---------------- PTX helpers (sm_80-class only: assemble under compute_103) --
__device__ __forceinline__ uint32_t s2u(const void* p) {
    uint32_t a;
    asm("{ .reg .u64 t; cvta.to.shared.u64 t, %1; cvt.u32.u64 %0, t; }"
        : "=r"(a) : "l"(p));
    return a;
}

__device__ __forceinline__ void cpa16(uint32_t dst, const void* src, int sz) {
    asm volatile("cp.async.cg.shared.global [%0], [%1], 16, %2;"
                 :: "r"(dst), "l"(src), "r"(sz));
}

__device__ __forceinline__ void cp_commit() {
    asm volatile("cp.async.commit_group;" ::: "memory");
}

__device__ __forceinline__ void cp_wait1() {
    asm volatile("cp.async.wait_group 1;" ::: "memory");
}

__device__ __forceinline__ void ldsm4(uint32_t* r, uint32_t a) {
    asm volatile("ldmatrix.sync.aligned.m8n8.x4.shared.b16 {%0,%1,%2,%3}, [%4];"
                 : "=r"(r[0]), "=r"(r[1]), "=r"(r[2]), "=r"(r[3]) : "r"(a));
}

__device__ __forceinline__ void mma_bf16(float* c, const uint32_t* a, const uint32_t* b) {
    asm volatile(
        "mma.sync.aligned.m16n8k16.row.col.f32.bf16.bf16.f32 "
        "{%0,%1,%2,%3}, {%4,%5,%6,%7}, {%8,%9}, {%0,%1,%2,%3};"
        : "+f"(c[0]), "+f"(c[1]), "+f"(c[2]), "+f"(c[3])
        : "r"(a[0]), "r"(a[1]), "r"(a[2]), "r"(a[3]), "r"(b[0]), "r"(b[1]));
}

// ---------------------------------------------------------------------------
// issue one K-chunk stage: Ah/Al rows [m0,m0+128), Bh/Bl rows [n0,n0+128)
// 2048 16B chunks, 8 per thread. OOB rows zero-filled (cp.async src-size 0).
// ---------------------------------------------------------------------------
__device__ __forceinline__ void issue_stage(
    uint32_t sbase, int stg, int kt,
    const __nv_bfloat16* __restrict__ Ah, const __nv_bfloat16* __restrict__ Al,
    const __nv_bfloat16* __restrict__ Bh, const __nv_bfloat16* __restrict__ Bl,
    int m0, int n0, int M, int Ncols, int tid)
{
    uint32_t base = sbase + stg * STGB;
#pragma unroll
    for (int i = 0; i < 8; i++) {
        int chunk = tid + i * 256;
        int op  = chunk >> 9;
        int idx = chunk & 511;
        int row = idx >> 2;
        int c   = idx & 3;
        const __nv_bfloat16* src;
        int gr; bool pred;
        if (op < 2) { gr = m0 + row; pred = (gr < M);     src = (op == 0) ? Ah : Al; }
        else        { gr = n0 + row; pred = (gr < Ncols); src = (op == 2) ? Bh : Bl; }
        if (!pred) gr = 0;
        const void* sp = src + (size_t)gr * KDIM + kt * KC + c * 8;
        uint32_t dp = base + op * OPB + row * 80 + c * 16;
        cpa16(dp, sp, pred ? 16 : 0);
    }
}

// ---------------------------------------------------------------------------
// split-bf16 tensor GEMM: D[M tile 128][N tile 128] = A[M,1024] @ B^T[N,1024]^T
// EPI 0: Cout = g_E (stride G4), M edge
// EPI 1: Cout = g_gates, += g_E[tok] + bx + bh
// EPI 2: Cout = out (stride NCLS), += b_out, N edge
// ---------------------------------------------------------------------------
template <int EPI>
__global__ void __launch_bounds__(256, 1)
tgemm(const __nv_bfloat16* __restrict__ Ah, const __nv_bfloat16* __restrict__ Al,
      const __nv_bfloat16* __restrict__ Bh, const __nv_bfloat16* __restrict__ Bl,
      float* __restrict__ Cout, int M, int Ncols,
      const float* __restrict__ bias1, const float* __restrict__ bias2,
      const int* __restrict__ Xtok, int s)
{
    extern __shared__ char smem[];
    const int tid  = threadIdx.x;
    const int lane = tid & 31;
    const int wid  = tid >> 5;
    const int wm   = wid & 3;      // 4 warps in M, 32 rows each
    const int wn   = wid >> 2;     // 2 warps in N, 64 cols each
    const int m0   = blockIdx.y * TM;
    const int n0   = blockIdx.x * TN;
    uint32_t sbase = s2u(smem);

    float acc[2][8][4];
#pragma unroll
    for (int f = 0; f < 2; f++)
#pragma unroll
        for (int j = 0; j < 8; j++)
#pragma unroll
            for (int q = 0; q < 4; q++) acc[f][j][q] = 0.0f;

    // prologue: stages 0,1
    issue_stage(sbase, 0, 0, Ah, Al, Bh, Bl, m0, n0, M, Ncols, tid);
    cp_commit();
    issue_stage(sbase, 1, 1, Ah, Al, Bh, Bl, m0, n0, M, Ncols, tid);
    cp_commit();

    // precomputed ldmatrix lane addressing (byte offsets within a stage)
    const int arow  = wm * 32 + (lane & 15);
    const uint32_t acolh = 16 * (lane >> 4);             // bytes: 8 bf16 * (l>>4)
    const int brow0 = wn * 64 + (lane & 7) + 8 * (lane >> 4);
    const uint32_t bcolh = 16 * ((lane >> 3) & 1);

    int stg = 0;
    for (int kt = 0; kt < NK; kt++) {
        cp_wait1();
        __syncthreads();
        if (kt + 2 < NK) {
            int ns = stg + 2; if (ns >= STAGES) ns -= STAGES;
            issue_stage(sbase, ns, kt + 2, Ah, Al, Bh, Bl, m0, n0, M, Ncols, tid);
        }
        cp_commit();

        uint32_t sb = sbase + stg * STGB;
#pragma unroll
        for (int kk = 0; kk < KC; kk += 16) {
            uint32_t kb = kk * 2;  // byte offset of k16 within 80B row
            uint32_t ah[2][4], al[2][4], bh[4][4], bl[4][4];
            ldsm4(ah[0], sb + 0 * OPB + (uint32_t)(arow)      * 80 + kb + acolh);
            ldsm4(ah[1], sb + 0 * OPB + (uint32_t)(arow + 16) * 80 + kb + acolh);
            ldsm4(al[0], sb + 1 * OPB + (uint32_t)(arow)      * 80 + kb + acolh);
            ldsm4(al[1], sb + 1 * OPB + (uint32_t)(arow + 16) * 80 + kb + acolh);
#pragma unroll
            for (int j4 = 0; j4 < 4; j4++) {
                ldsm4(bh[j4], sb + 2 * OPB + (uint32_t)(brow0 + j4 * 16) * 80 + kb + bcolh);
                ldsm4(bl[j4], sb + 3 * OPB + (uint32_t)(brow0 + j4 * 16) * 80 + kb + bcolh);
            }
#pragma unroll
            for (int f = 0; f < 2; f++)
#pragma unroll
                for (int j = 0; j < 8; j++) {
                    const uint32_t* bhp = &bh[j >> 1][(j & 1) * 2];
                    const uint32_t* blp = &bl[j >> 1][(j & 1) * 2];
                    mma_bf16(acc[f][j], ah[f], bhp);
                    mma_bf16(acc[f][j], al[f], bhp);
                    mma_bf16(acc[f][j], ah[f], blp);
                }
        }
        stg++; if (stg >= STAGES) stg = 0;
    }

    // ---- epilogue: registers -> GMEM ----
    const int g = lane >> 2, t = lane & 3;
#pragma unroll
    for (int f = 0; f < 2; f++) {
#pragma unroll
        for (int h = 0; h < 2; h++) {
            int row = m0 + wm * 32 + f * 16 + g + h * 8;
            if (EPI == 0 && row >= M) continue;
            const float* er = nullptr;
            if (EPI == 1) {
                int tok = __ldg(&Xtok[row * SEQ + s]);
                er = g_E + (size_t)tok * G4;
            }
#pragma unroll
            for (int j = 0; j < 8; j++) {
                int col = n0 + wn * 64 + j * 8 + 2 * t;
                float v0 = acc[f][j][h * 2 + 0];
                float v1 = acc[f][j][h * 2 + 1];
                if (EPI == 0) {
                    float2 o = make_float2(v0, v1);
                    *(float2*)(Cout + (size_t)row * G4 + col) = o;
                } else if (EPI == 1) {
                    float2 e  = *(const float2*)(er + col);
                    float2 b1 = *(const float2*)(bias1 + col);
                    float2 b2 = *(const float2*)(bias2 + col);
                    float2 o = make_float2(v0 + e.x + b1.x + b2.x,
                                           v1 + e.y + b1.y + b2.y);
                    *(float2*)(Cout + (size_t)row * G4 + col) = o;
                } else {
                    size_t rb = (size_t)row * Ncols;
                    if (col < Ncols)     Cout[rb + col]     = v0 + bias1[col];
                    if (col + 1 < Ncols) Cout[rb + col + 1] = v1 + bias1[col + 1];
                }
            }
        }
    }
}

// ---------------------------------------------------------------------------
// split fp32 -> bf16 hi/lo (no transpose), for C. 4 elems/thread.
__global__ void splitC_k(const float* __restrict__ in) {
    size_t i4 = (size_t)blockIdx.x * 256 + threadIdx.x;
    float4 v = *(const float4*)(in + i4 * 4);
    float f[4] = {v.x, v.y, v.z, v.w};
    __nv_bfloat16 hi[4]; float lo[4];
#pragma unroll
    for (int j = 0; j < 4; j++) {
        hi[j] = __float2bfloat16(f[j]);
        lo[j] = f[j] - __bfloat162float(hi[j]);
    }
    __nv_bfloat162* ph = (__nv_bfloat162*)(g_Ch + i4 * 4);
    __nv_bfloat162* pl = (__nv_bfloat162*)(g_Cl + i4 * 4);
    ph[0] = __nv_bfloat162(hi[0], hi[1]);
    ph[1] = __nv_bfloat162(hi[2], hi[3]);
    pl[0] = __floats2bfloat162_rn(lo[0], lo[1]);
    pl[1] = __floats2bfloat162_rn(lo[2], lo[3]);
}

// transpose + split: in[Kd][Nd] fp32 -> oh/ol[Nd][Kd] bf16
__global__ void tsplit_k(const float* __restrict__ in,
                         __nv_bfloat16* __restrict__ oh,
                         __nv_bfloat16* __restrict__ ol,
                         int Kd, int Nd)
{
    __shared__ float tbuf[32][33];
    int nb = blockIdx.x * 32, kb = blockIdx.y * 32;
    int tx = threadIdx.x, ty = threadIdx.y;
#pragma unroll
    for (int i = 0; i < 4; i++) {
        int r = kb + ty + i * 8, c = nb + tx;
        if (r < Kd && c < Nd) tbuf[ty + i * 8][tx] = in[(size_t)r * Nd + c];
    }
    __syncthreads();
#pragma unroll
    for (int i = 0; i < 4; i++) {
        int orow = nb + ty + i * 8, ocol = kb + tx;
        if (orow < Nd && ocol < Kd) {
            float v = tbuf[tx][ty + i * 8];
            __nv_bfloat16 hi = __float2bfloat16(v);
            oh[(size_t)orow * Kd + ocol] = hi;
            ol[(size_t)orow * Kd + ocol] = __float2bfloat16(v - __bfloat162float(hi));
        }
    }
}

__global__ void init_k() {
    int idx = blockIdx.x * 256 + threadIdx.x;
    if (idx < BATCH * KDIM) {
        g_c[idx] = 0.0f;
        g_hh[idx] = __float2bfloat16(0.0f);
        g_hl[idx] = __float2bfloat16(0.0f);
    }
}

__device__ __forceinline__ float sigf(float x) { return 1.0f / (1.0f + __expf(-x)); }

__global__ void cell_k() {
    int idx = blockIdx.x * 256 + threadIdx.x;             // over BATCH*HID/4
    int b = idx >> 8;
    int j4 = (idx & 255) * 4;
    const float* gr = g_gates + (size_t)b * G4;
    float4 gi = *(const float4*)(gr + j4);
    float4 gf = *(const float4*)(gr + 1024 + j4);
    float4 gg = *(const float4*)(gr + 2048 + j4);
    float4 go = *(const float4*)(gr + 3072 + j4);
    float4 c = *(float4*)(g_c + (size_t)idx * 4);
    float hv[4];
    {
        float i0 = sigf(gi.x), f0 = sigf(gf.x), g0 = tanhf(gg.x), o0 = sigf(go.x);
        c.x = f0 * c.x + i0 * g0; hv[0] = o0 * tanhf(c.x);
        float i1 = sigf(gi.y), f1 = sigf(gf.y), g1 = tanhf(gg.y), o1 = sigf(go.y);
        c.y = f1 * c.y + i1 * g1; hv[1] = o1 * tanhf(c.y);
        float i2 = sigf(gi.z), f2 = sigf(gf.z), g2 = tanhf(gg.z), o2 = sigf(go.z);
        c.z = f2 * c.z + i2 * g2; hv[2] = o2 * tanhf(c.z);
        float i3 = sigf(gi.w), f3 = sigf(gf.w), g3 = tanhf(gg.w), o3 = sigf(go.w);
        c.w = f3 * c.w + i3 * g3; hv[3] = o3 * tanhf(c.w);
    }
    *(float4*)(g_c + (size_t)idx * 4) = c;
    __nv_bfloat16 hi[4]; float lo[4];
#pragma unroll
    for (int j = 0; j < 4; j++) {
        hi[j] = __float2bfloat16(hv[j]);
        lo[j] = hv[j] - __bfloat162float(hi[j]);
    }
    __nv_bfloat162* ph = (__nv_bfloat162*)(g_hh + (size_t)idx * 4);
    __nv_bfloat162* pl = (__nv_bfloat162*)(g_hl + (size_t)idx * 4);
    ph[0] = __nv_bfloat162(hi[0], hi[1]);
    ph[1] = __nv_bfloat162(hi[2], hi[3]);
    pl[0] = __floats2bfloat162_rn(lo[0], lo[1]);
    pl[1] = __floats2bfloat162_rn(lo[2], lo[3]);
}

// ---------------------------------------------------------------------------
extern "C" void kernel_launch(void* const* d_in, const int* in_sizes, int n_in,
                              void* d_out, int out_size)
{
    const int*   X     = (const int*)  d_in[0];
    const float* C     = (const float*)d_in[1];
    const float* Wx    = (const float*)d_in[2];
    const float* bx    = (const float*)d_in[3];
    const float* Wh    = (const float*)d_in[4];
    const float* bh    = (const float*)d_in[5];
    const float* W_out = (const float*)d_in[6];
    const float* b_out = (const float*)d_in[7];
    float* out = (float*)d_out;
    (void)in_sizes; (void)n_in; (void)out_size;

    cudaFuncSetAttribute(tgemm<0>, cudaFuncAttributeMaxDynamicSharedMemorySize, SMEM_BYTES);
    cudaFuncSetAttribute(tgemm<1>, cudaFuncAttributeMaxDynamicSharedMemorySize, SMEM_BYTES);
    cudaFuncSetAttribute(tgemm<2>, cudaFuncAttributeMaxDynamicSharedMemorySize, SMEM_BYTES);

    void *pCh, *pCl, *pWxTh, *pWxTl, *pWhTh, *pWhTl, *pWoTh, *pWoTl, *pE, *pG, *pHh, *pHl;
    cudaGetSymbolAddress(&pCh, g_Ch);     cudaGetSymbolAddress(&pCl, g_Cl);
    cudaGetSymbolAddress(&pWxTh, g_WxTh); cudaGetSymbolAddress(&pWxTl, g_WxTl);
    cudaGetSymbolAddress(&pWhTh, g_WhTh); cudaGetSymbolAddress(&pWhTl, g_WhTl);
    cudaGetSymbolAddress(&pWoTh, g_WoTh); cudaGetSymbolAddress(&pWoTl, g_WoTl);
    cudaGetSymbolAddress(&pE, g_E);       cudaGetSymbolAddress(&pG, g_gates);
    cudaGetSymbolAddress(&pHh, g_hh);     cudaGetSymbolAddress(&pHl, g_hl);

    // ---- conversions ----
    splitC_k<<<NCLS, 256>>>(C);
    {
        dim3 blk(32, 8);
        tsplit_k<<<dim3(G4 / 32, KDIM / 32), blk>>>(Wx, (__nv_bfloat16*)pWxTh,
                                                    (__nv_bfloat16*)pWxTl, KDIM, G4);
        tsplit_k<<<dim3(G4 / 32, KDIM / 32), blk>>>(Wh, (__nv_bfloat16*)pWhTh,
                                                    (__nv_bfloat16*)pWhTl, KDIM, G4);
        tsplit_k<<<dim3((NCLS + 31) / 32, KDIM / 32), blk>>>(W_out, (__nv_bfloat16*)pWoTh,
                                                             (__nv_bfloat16*)pWoTl, KDIM, NCLS);
    }
    init_k<<<(BATCH * KDIM + 255) / 256, 256>>>();

    // ---- phase 1: E = C @ Wx ----
    {
        dim3 grid(G4 / TN, (NCLS + TM - 1) / TM);   // (32, 393)
        tgemm<0><<<grid, 256, SMEM_BYTES>>>(
            (const __nv_bfloat16*)pCh, (const __nv_bfloat16*)pCl,
            (const __nv_bfloat16*)pWxTh, (const __nv_bfloat16*)pWxTl,
            (float*)pE, NCLS, G4, nullptr, nullptr, nullptr, 0);
    }

    // ---- phase 2: recurrence ----
    {
        dim3 grid(G4 / TN, BATCH / TM);             // (32, 8)
        for (int s = 0; s < SEQ; s++) {
            tgemm<1><<<grid, 256, SMEM_BYTES>>>(
                (const __nv_bfloat16*)pHh, (const __nv_bfloat16*)pHl,
                (const __nv_bfloat16*)pWhTh, (const __nv_bfloat16*)pWhTl,
                (float*)pG, BATCH, G4, bx, bh, X, s);
            cell_k<<<BATCH * KDIM / 4 / 256, 256>>>();
        }
    }

    // ---- phase 3: out = h @ W_out + b_out ----
    {
        dim3 grid((NCLS + TN - 1) / TN, BATCH / TM);  // (393, 8)
        tgemm<2><<<grid, 256, SMEM_BYTES>>>(
            (const __nv_bfloat16*)pHh, (const __nv_bfloat16*)pHl,
            (const __nv_bfloat16*)pWoTh, (const __nv_bfloat16*)pWoTl,
            out, BATCH, NCLS, b_out, nullptr, nullptr, 0);
    }
}